// round 9
// baseline (speedup 1.0000x reference)
#include <cuda_runtime.h>
#include <string.h>

#define NN 512
#define H  64
#define ED 6
#define NL 4
#define EE (NN*NN)
#define LN_EPS 1e-5f

// Scratch (device globals: no allocations allowed)
__device__ float g_h  [NN*H];
__device__ float g_Hd [NN*H];         // dst-side attention proj (+att_b1), row-major
__device__ float g_HsT[2][H*NN];      // src-side attention proj, DIM-MAJOR [j][s], double buffered
__device__ float g_Av [2][NN*H];      // src-side value proj (+val_b1), row-major, double buffered
__device__ float g_eaT[ED*EE];        // edge_attr transposed: eaT[k][d][s]

__device__ __forceinline__ float warp_sum(float v) {
#pragma unroll
    for (int o = 16; o; o >>= 1) v += __shfl_xor_sync(0xffffffffu, v, o);
    return v;
}
__device__ __forceinline__ float warp_max(float v) {
#pragma unroll
    for (int o = 16; o; o >>= 1) v = fmaxf(v, __shfl_xor_sync(0xffffffffu, v, o));
    return v;
}

// Packed fp32x2 ops (sm_103a): 2 fp32 FMAs per instruction
__device__ __forceinline__ float2 ffma2(float2 a, float2 b, float2 c) {
    unsigned long long ua, ub, uc, ur;
    memcpy(&ua, &a, 8); memcpy(&ub, &b, 8); memcpy(&uc, &c, 8);
    asm("fma.rn.f32x2 %0, %1, %2, %3;" : "=l"(ur) : "l"(ua), "l"(ub), "l"(uc));
    float2 r; memcpy(&r, &ur, 8); return r;
}
__device__ __forceinline__ float2 fadd2(float2 a, float2 b) {
    unsigned long long ua, ub, ur;
    memcpy(&ua, &a, 8); memcpy(&ub, &b, 8);
    asm("add.rn.f32x2 %0, %1, %2;" : "=l"(ur) : "l"(ua), "l"(ub));
    float2 r; memcpy(&r, &ur, 8); return r;
}
__device__ __forceinline__ float2 fmul2(float2 a, float2 b) {
    unsigned long long ua, ub, ur;
    memcpy(&ua, &a, 8); memcpy(&ub, &b, 8);
    asm("mul.rn.f32x2 %0, %1, %2;" : "=l"(ur) : "l"(ua), "l"(ub));
    float2 r; memcpy(&r, &ur, 8); return r;
}

// Per-node tables: Hd = h@Wa[0:64]+b1a (row), HsT = h@Wa[64:128] (dim-major), Av = h@Wv[0:64]+b1v (row)
__device__ __forceinline__ void compute_tables(
    int d, int t, int wb, const float* h_sh,
    const float* __restrict__ attW1, const float* __restrict__ attB1,
    const float* __restrict__ valW1, const float* __restrict__ valB1)
{
    float ad = attB1[t], as = 0.f, av = valB1[t];
#pragma unroll 8
    for (int k = 0; k < H; k++) {
        float hk = h_sh[k];
        ad += hk * attW1[k * H + t];
        as += hk * attW1[(H + k) * H + t];
        av += hk * valW1[k * H + t];
    }
    g_Hd[d * H + t]       = ad;
    g_HsT[wb][t * NN + d] = as;
    g_Av[wb][d * H + t]   = av;
}

// Transpose edge_attr: ea[s][d][k] -> eaT[k][d][s]. grid (16,16), block 256.
__global__ void __launch_bounds__(256) ea_transpose_kernel(const float* __restrict__ ea)
{
    __shared__ float t_sh[ED][32][33];
    const int t = threadIdx.x, w = t >> 5, lane = t & 31;
    const int bs = blockIdx.x * 32, bd = blockIdx.y * 32;

#pragma unroll
    for (int rr = 0; rr < 4; rr++) {
        int s_loc = w + rr * 8;
        const float* base = ea + ((size_t)(bs + s_loc) * NN + bd) * ED + lane * ED;
        float2 v0 = *(const float2*)(base);
        float2 v1 = *(const float2*)(base + 2);
        float2 v2 = *(const float2*)(base + 4);
        t_sh[0][lane][s_loc] = v0.x; t_sh[1][lane][s_loc] = v0.y;
        t_sh[2][lane][s_loc] = v1.x; t_sh[3][lane][s_loc] = v1.y;
        t_sh[4][lane][s_loc] = v2.x; t_sh[5][lane][s_loc] = v2.y;
    }
    __syncthreads();
#pragma unroll
    for (int idx = t; idx < ED * 32 * 32; idx += 256) {
        int k = idx >> 10, r = idx & 1023, dl = r >> 5, sl = r & 31;
        g_eaT[(size_t)k * EE + (size_t)(bd + dl) * NN + bs + sl] = t_sh[k][dl][sl];
    }
}

// Encoder: h = relu(x@W1+b1)@W2+b2, then layer-0 tables (buffer 0). grid=512, block=64
__global__ void __launch_bounds__(H) enc_kernel(
    const float* __restrict__ x,
    const float* __restrict__ ew1, const float* __restrict__ eb1,
    const float* __restrict__ ew2, const float* __restrict__ eb2,
    const float* __restrict__ attW1, const float* __restrict__ attB1,
    const float* __restrict__ valW1, const float* __restrict__ valB1)
{
    int d = blockIdx.x, t = threadIdx.x;
    __shared__ float xs[ED], hid[H], hsn[H];
    if (t < ED) xs[t] = x[d * ED + t];
    __syncthreads();
    float a = eb1[t];
#pragma unroll
    for (int k = 0; k < ED; k++) a += xs[k] * ew1[k * H + t];
    hid[t] = fmaxf(a, 0.f);
    __syncthreads();
    float hv = eb2[t];
#pragma unroll 8
    for (int k = 0; k < H; k++) hv += hid[k] * ew2[k * H + t];
    g_h[d * H + t] = hv;
    hsn[t] = hv;
    __syncthreads();
    compute_tables(d, t, 0, hsn, attW1, attB1, valW1, valB1);
}

// Fused layer: one block per dst node d. 256 threads = 8 warps; warp w owns
// srcs [w*64, w*64+64); lane owns the pair (2*lane, 2*lane+1). All f32x2
// operands pre-duplicated in smem (zero dup-MOVs: float4 component pairs are
// aligned register pairs). Per-warp register softmax, block combine in smem,
// then node MLP + LN + next-layer tables fused (overlaps across the 4
// co-resident blocks/SM). __launch_bounds__(256,4): regs<=64 -> single wave.
__global__ void __launch_bounds__(256, 4) layer_kernel(
    const float* __restrict__ attW1e,   // [6,64] edge rows of att_w1[l]
    const float* __restrict__ attW2,    // [64]
    const float* __restrict__ valW1e,   // [6,64] edge rows of val_w1[l]
    const float* __restrict__ valW2, const float* __restrict__ valB2,
    const float* __restrict__ updW1, const float* __restrict__ updB1,
    const float* __restrict__ updW2, const float* __restrict__ updB2,
    const float* __restrict__ lng, const float* __restrict__ lnb,
    const float* __restrict__ nattW1, const float* __restrict__ nattB1,
    const float* __restrict__ nvalW1, const float* __restrict__ nvalB1,
    const float* __restrict__ decW1, const float* __restrict__ decB1,
    const float* __restrict__ decW2, const float* __restrict__ decB2,
    float* __restrict__ out, int rb, int last)
{
    const int d = blockIdx.x;
    const int t = threadIdx.x, w = t >> 5, lane = t & 31;
    const int wb = rb ^ 1;

    __shared__ __align__(16) float4 wa4[H * 4];    // per j: dup pairs (w0,w0,w1,w1)(w2..w3)(w4..w5)(wo,wo,hd,hd)
    __shared__ __align__(16) float4 ea2[NN * 3];   // per s: dup ea pairs
    __shared__ __align__(16) float2 wexp2[NN];     // per s: duplicated softmax weight
    __shared__ float pm[8], ps[8], pacc[8 * H];
    __shared__ float part4[4 * H], agg_sh[H], h_sh[H], tmp_sh[H], hid_sh[H], hn_sh[H], red_sh[4];

    // Prologue: duplicated weight table + Hd row
    if (t < H) {
        int j = t;
        float w0 = attW1e[0 * H + j], w1 = attW1e[1 * H + j];
        float w2 = attW1e[2 * H + j], w3 = attW1e[3 * H + j];
        float w4 = attW1e[4 * H + j], w5 = attW1e[5 * H + j];
        float wo = attW2[j];
        float hd = g_Hd[d * H + j];
        wa4[j * 4 + 0] = make_float4(w0, w0, w1, w1);
        wa4[j * 4 + 1] = make_float4(w2, w2, w3, w3);
        wa4[j * 4 + 2] = make_float4(w4, w4, w5, w5);
        wa4[j * 4 + 3] = make_float4(wo, wo, hd, hd);
    }

    const float* HsT = g_HsT[rb];
    const float* AvL = g_Av[rb];
    const int sg = w * 64 + 2 * lane;    // src pair (sg, sg+1)

    // Load ea for the 2 srcs (float2 from eaT, contiguous)
    float2 eav[ED];
#pragma unroll
    for (int k = 0; k < ED; k++)
        eav[k] = *(const float2*)(g_eaT + (size_t)k * EE + d * NN + sg);

    // Publish duplicated ea pairs for pass 2
    ea2[(sg + 0) * 3 + 0] = make_float4(eav[0].x, eav[0].x, eav[1].x, eav[1].x);
    ea2[(sg + 0) * 3 + 1] = make_float4(eav[2].x, eav[2].x, eav[3].x, eav[3].x);
    ea2[(sg + 0) * 3 + 2] = make_float4(eav[4].x, eav[4].x, eav[5].x, eav[5].x);
    ea2[(sg + 1) * 3 + 0] = make_float4(eav[0].y, eav[0].y, eav[1].y, eav[1].y);
    ea2[(sg + 1) * 3 + 1] = make_float4(eav[2].y, eav[2].y, eav[3].y, eav[3].y);
    ea2[(sg + 1) * 3 + 2] = make_float4(eav[4].y, eav[4].y, eav[5].y, eav[5].y);
    __syncthreads();

    // ---- Pass 1: attention logits for the 2 srcs, full j-loop ----
    float2 lg = make_float2(0.f, 0.f);
    const float2 c02 = make_float2(0.2f, 0.2f);
#pragma unroll 8
    for (int j = 0; j < H; j++) {
        float4 c0 = wa4[j * 4 + 0];
        float4 c1 = wa4[j * 4 + 1];
        float4 c2 = wa4[j * 4 + 2];
        float4 c3 = wa4[j * 4 + 3];
        float2 hs2 = *(const float2*)(HsT + j * NN + sg);
        // two 3-deep independent chains
        float2 z  = fadd2(hs2, make_float2(c3.z, c3.w));
        float2 z2 = fmul2(eav[3], make_float2(c1.z, c1.w));
        z  = ffma2(eav[0], make_float2(c0.x, c0.y), z);
        z2 = ffma2(eav[4], make_float2(c2.x, c2.y), z2);
        z  = ffma2(eav[1], make_float2(c0.z, c0.w), z);
        z2 = ffma2(eav[5], make_float2(c2.z, c2.w), z2);
        z  = ffma2(eav[2], make_float2(c1.x, c1.y), z);
        z  = fadd2(z, z2);
        // leaky_relu(., 0.2)
        float2 s = fmul2(z, c02);
        z.x = fmaxf(z.x, s.x);
        z.y = fmaxf(z.y, s.y);
        lg = ffma2(z, make_float2(c3.x, c3.y), lg);
    }

    // ---- Per-warp register softmax over this warp's 64 srcs ----
    {
        float m = warp_max(fmaxf(lg.x, lg.y));
        float e0 = __expf(lg.x - m), e1 = __expf(lg.y - m);
        float s_w = warp_sum(e0 + e1);
        if (lane == 0) { pm[w] = m; ps[w] = s_w; }
        *(float4*)(wexp2 + sg) = make_float4(e0, e0, e1, e1);
    }
    __syncthreads();

    // ---- Pass 2: alpha-weighted value aggregation (f32x2, 2 dims/lane) ----
    const int j0 = 2 * lane;
    float2 wv[ED];
#pragma unroll
    for (int k = 0; k < ED; k++) wv[k] = *(const float2*)(valW1e + k * H + j0);

    float2 acc0 = make_float2(0.f, 0.f), acc1 = make_float2(0.f, 0.f);
    const int base = w * 64;
    const float* avbase = AvL + j0;
#pragma unroll 4
    for (int i = 0; i < 64; i += 2) {
#pragma unroll
        for (int u = 0; u < 2; u++) {
            int s = base + i + u;
            float4 q0 = ea2[s * 3 + 0];
            float4 q1 = ea2[s * 3 + 1];
            float4 q2 = ea2[s * 3 + 2];
            float2 p = *(const float2*)(avbase + (size_t)s * H);
            p = ffma2(make_float2(q0.x, q0.y), wv[0], p);
            p = ffma2(make_float2(q0.z, q0.w), wv[1], p);
            p = ffma2(make_float2(q1.x, q1.y), wv[2], p);
            p = ffma2(make_float2(q1.z, q1.w), wv[3], p);
            p = ffma2(make_float2(q2.x, q2.y), wv[4], p);
            p = ffma2(make_float2(q2.z, q2.w), wv[5], p);
            p.x = fmaxf(p.x, 0.f);
            p.y = fmaxf(p.y, 0.f);
            float2 wt2 = wexp2[s];
            if (u) acc1 = ffma2(wt2, p, acc1);
            else   acc0 = ffma2(wt2, p, acc0);
        }
    }
    acc0 = fadd2(acc0, acc1);
    *(float2*)(pacc + w * H + j0) = acc0;
    __syncthreads();

    // ---- Combine 8 warp softmax partials (threads 0..63) ----
    if (t < H) {
        float M = pm[0];
#pragma unroll
        for (int k = 1; k < 8; k++) M = fmaxf(M, pm[k]);
        float stot = 0.f, a = 0.f;
#pragma unroll
        for (int k = 0; k < 8; k++) {
            float sc = __expf(pm[k] - M);
            stot += ps[k] * sc;
            a    += pacc[k * H + t] * sc;
        }
        agg_sh[t] = a / stot;
        h_sh[t]   = g_h[d * H + t];
    }
    __syncthreads();

    // ---- Node phase, 4-way k-split matvecs over all 256 threads ----
    const int o = t & 63, q = t >> 6;

    // stage 1: tmp = val_b2 + agg @ val_w2
    {
        float p = 0.f;
        int k0 = q * 16;
#pragma unroll
        for (int kk = 0; kk < 16; kk++) p += agg_sh[k0 + kk] * valW2[(k0 + kk) * H + o];
        part4[q * H + o] = p;
    }
    __syncthreads();
    if (t < H) tmp_sh[t] = valB2[t] + part4[t] + part4[H + t] + part4[2 * H + t] + part4[3 * H + t];
    __syncthreads();

    // stage 2: hid = relu(upd_b1 + [h,tmp] @ upd_w1)
    {
        const float* srcv = (q < 2) ? h_sh : tmp_sh;
        int koff = (q & 1) * 32;
        int rbase = ((q >= 2) ? H : 0) + koff;
        float p = 0.f;
#pragma unroll
        for (int kk = 0; kk < 32; kk++) p += srcv[koff + kk] * updW1[(rbase + kk) * H + o];
        part4[q * H + o] = p;
    }
    __syncthreads();
    if (t < H) hid_sh[t] = fmaxf(updB1[t] + part4[t] + part4[H + t] + part4[2 * H + t] + part4[3 * H + t], 0.f);
    __syncthreads();

    // stage 3: u = upd_b2 + hid @ upd_w2
    {
        float p = 0.f;
        int k0 = q * 16;
#pragma unroll
        for (int kk = 0; kk < 16; kk++) p += hid_sh[k0 + kk] * updW2[(k0 + kk) * H + o];
        part4[q * H + o] = p;
    }
    __syncthreads();

    // residual + LayerNorm (threads 0..63 = warps 0,1; fused sum/sumsq)
    float r = 0.f, dr = 0.f;
    if (t < H) {
        float u = updB2[t] + part4[t] + part4[H + t] + part4[2 * H + t] + part4[3 * H + t];
        r = u + h_sh[t];
        float s1 = warp_sum(r);
        float s2 = warp_sum(r * r);
        if (lane == 0) { red_sh[w] = s1; red_sh[w + 2] = s2; }
    }
    __syncthreads();
    if (t < H) {
        float mu  = (red_sh[0] + red_sh[1]) * (1.0f / H);
        float ex2 = (red_sh[2] + red_sh[3]) * (1.0f / H);
        float var = ex2 - mu * mu;
        dr = r - mu;
        float hn = lng[t] * dr * rsqrtf(var + LN_EPS) + lnb[t];
        hn_sh[t] = hn;
        if (!last) g_h[d * H + t] = hn;
    }
    __syncthreads();

    if (!last) {
        if (t < H)
            compute_tables(d, t, wb, hn_sh, nattW1, nattB1, nvalW1, nvalB1);
    } else {
        if (t < H) {
            float dh = decB1[t];
#pragma unroll 8
            for (int k = 0; k < H; k++) dh += hn_sh[k] * decW1[k * H + t];
            dh = fmaxf(dh, 0.f);
            float p = dh * decW2[t];
            float psum = warp_sum(p);
            if (lane == 0) red_sh[w] = psum;
        }
        __syncthreads();
        if (t == 0) out[d] = red_sh[0] + red_sh[1] + decB2[0];
    }
}

extern "C" void kernel_launch(void* const* d_in, const int* in_sizes, int n_in,
                              void* d_out, int out_size)
{
    const float* x      = (const float*)d_in[0];
    const float* ea     = (const float*)d_in[1];
    const float* enc_w1 = (const float*)d_in[2];
    const float* enc_b1 = (const float*)d_in[3];
    const float* enc_w2 = (const float*)d_in[4];
    const float* enc_b2 = (const float*)d_in[5];
    const float* att_w1 = (const float*)d_in[6];   // [4,134,64]
    const float* att_b1 = (const float*)d_in[7];   // [4,64]
    const float* att_w2 = (const float*)d_in[8];   // [4,64,1]
    // d_in[9] = att_b2 — cancels inside softmax, unused
    const float* val_w1 = (const float*)d_in[10];  // [4,70,64]
    const float* val_b1 = (const float*)d_in[11];  // [4,64]
    const float* val_w2 = (const float*)d_in[12];  // [4,64,64]
    const float* val_b2 = (const float*)d_in[13];  // [4,64]
    const float* upd_w1 = (const float*)d_in[14];  // [4,128,64]
    const float* upd_b1 = (const float*)d_in[15];  // [4,64]
    const float* upd_w2 = (const float*)d_in[16];  // [4,64,64]
    const float* upd_b2 = (const float*)d_in[17];  // [4,64]
    const float* ln_g   = (const float*)d_in[18];  // [4,64]
    const float* ln_b   = (const float*)d_in[19];  // [4,64]
    const float* dec_w1 = (const float*)d_in[20];
    const float* dec_b1 = (const float*)d_in[21];
    const float* dec_w2 = (const float*)d_in[22];
    const float* dec_b2 = (const float*)d_in[23];
    // d_in[24] = edge_index: src=e/512, dst=e%512 (structure exploited directly)

    float* out = (float*)d_out;

    ea_transpose_kernel<<<dim3(16, 16), 256>>>(ea);
    enc_kernel<<<NN, H>>>(x, enc_w1, enc_b1, enc_w2, enc_b2,
                          att_w1, att_b1, val_w1, val_b1);

    for (int l = 0; l < NL; l++) {
        int last = (l == NL - 1);
        int nl = (l + 1) % NL;      // dummy-but-valid pointers on last layer
        int rb = l & 1;             // enc wrote buffer 0; layer l reads l&1, writes (l&1)^1
        layer_kernel<<<NN, 256>>>(att_w1 + (l * 134 + 128) * H,
                                  att_w2 + l * H,
                                  val_w1 + (l * 70 + 64) * H,
                                  val_w2 + l * H * H, val_b2 + l * H,
                                  upd_w1 + l * 2 * H * H, upd_b1 + l * H,
                                  upd_w2 + l * H * H, upd_b2 + l * H,
                                  ln_g + l * H, ln_b + l * H,
                                  att_w1 + nl * 134 * H, att_b1 + nl * H,
                                  val_w1 + nl * 70 * H, val_b1 + nl * H,
                                  dec_w1, dec_b1, dec_w2, dec_b2,
                                  out, rb, last);
    }
}

// round 10
// speedup vs baseline: 1.1552x; 1.1552x over previous
#include <cuda_runtime.h>
#include <string.h>

#define NN 512
#define H  64
#define ED 6
#define NL 4
#define EE (NN*NN)
#define LN_EPS 1e-5f

// Scratch (device globals: no allocations allowed)
__device__ float g_h  [NN*H];
__device__ float g_Hd [NN*H];         // dst-side attention proj (+att_b1), row-major
__device__ float g_HsT[2][H*NN];      // src-side attention proj, DIM-MAJOR [j][s], double buffered
__device__ float g_Av [2][NN*H];      // src-side value proj (+val_b1), row-major, double buffered
__device__ float g_eaT[ED*EE];        // edge_attr transposed: eaT[k][d][s]

// Dynamic shared memory layout for the fused 2-dst layer kernel (~70KB)
struct SmemLayout {
    float4 wa4[H * 4];       // per j: (w0,w0,w1,w1)(w2,w2,w3,w3)(w4,w4,w5,w5)(hdA,hdA,hdB,hdB)
    float2 wo2[H];           // per j: (wo,wo)
    float4 ea2[2][NN * 3];   // per dst, per s: dup ea pairs
    float2 wexp[2][NN];      // per dst, per s: duplicated softmax weight
    float  pm[2][8], ps[2][8];
    float  pacc[2][8 * H];
    float  agg[2][H], hsm[2][H], tmp[2][H], hid[2][H], hn[2][H];
    float  part[2][2 * H];
    float  red[2][4];
};

__device__ __forceinline__ float warp_sum(float v) {
#pragma unroll
    for (int o = 16; o; o >>= 1) v += __shfl_xor_sync(0xffffffffu, v, o);
    return v;
}
__device__ __forceinline__ float warp_max(float v) {
#pragma unroll
    for (int o = 16; o; o >>= 1) v = fmaxf(v, __shfl_xor_sync(0xffffffffu, v, o));
    return v;
}

// Packed fp32x2 ops (sm_103a): 2 fp32 FMAs per instruction
__device__ __forceinline__ float2 ffma2(float2 a, float2 b, float2 c) {
    unsigned long long ua, ub, uc, ur;
    memcpy(&ua, &a, 8); memcpy(&ub, &b, 8); memcpy(&uc, &c, 8);
    asm("fma.rn.f32x2 %0, %1, %2, %3;" : "=l"(ur) : "l"(ua), "l"(ub), "l"(uc));
    float2 r; memcpy(&r, &ur, 8); return r;
}
__device__ __forceinline__ float2 fadd2(float2 a, float2 b) {
    unsigned long long ua, ub, ur;
    memcpy(&ua, &a, 8); memcpy(&ub, &b, 8);
    asm("add.rn.f32x2 %0, %1, %2;" : "=l"(ur) : "l"(ua), "l"(ub));
    float2 r; memcpy(&r, &ur, 8); return r;
}
__device__ __forceinline__ float2 fmul2(float2 a, float2 b) {
    unsigned long long ua, ub, ur;
    memcpy(&ua, &a, 8); memcpy(&ub, &b, 8);
    asm("mul.rn.f32x2 %0, %1, %2;" : "=l"(ur) : "l"(ua), "l"(ub));
    float2 r; memcpy(&r, &ur, 8); return r;
}

// Per-node tables: Hd = h@Wa[0:64]+b1a (row), HsT = h@Wa[64:128] (dim-major), Av = h@Wv[0:64]+b1v (row)
__device__ __forceinline__ void compute_tables(
    int d, int t, int wb, const float* h_sh,
    const float* __restrict__ attW1, const float* __restrict__ attB1,
    const float* __restrict__ valW1, const float* __restrict__ valB1)
{
    float ad = attB1[t], as = 0.f, av = valB1[t];
#pragma unroll 8
    for (int k = 0; k < H; k++) {
        float hk = h_sh[k];
        ad += hk * attW1[k * H + t];
        as += hk * attW1[(H + k) * H + t];
        av += hk * valW1[k * H + t];
    }
    g_Hd[d * H + t]       = ad;
    g_HsT[wb][t * NN + d] = as;
    g_Av[wb][d * H + t]   = av;
}

// Transpose edge_attr: ea[s][d][k] -> eaT[k][d][s]. grid (16,16), block 256.
__global__ void __launch_bounds__(256) ea_transpose_kernel(const float* __restrict__ ea)
{
    __shared__ float t_sh[ED][32][33];
    const int t = threadIdx.x, w = t >> 5, lane = t & 31;
    const int bs = blockIdx.x * 32, bd = blockIdx.y * 32;

#pragma unroll
    for (int rr = 0; rr < 4; rr++) {
        int s_loc = w + rr * 8;
        const float* base = ea + ((size_t)(bs + s_loc) * NN + bd) * ED + lane * ED;
        float2 v0 = *(const float2*)(base);
        float2 v1 = *(const float2*)(base + 2);
        float2 v2 = *(const float2*)(base + 4);
        t_sh[0][lane][s_loc] = v0.x; t_sh[1][lane][s_loc] = v0.y;
        t_sh[2][lane][s_loc] = v1.x; t_sh[3][lane][s_loc] = v1.y;
        t_sh[4][lane][s_loc] = v2.x; t_sh[5][lane][s_loc] = v2.y;
    }
    __syncthreads();
#pragma unroll
    for (int idx = t; idx < ED * 32 * 32; idx += 256) {
        int k = idx >> 10, r = idx & 1023, dl = r >> 5, sl = r & 31;
        g_eaT[(size_t)k * EE + (size_t)(bd + dl) * NN + bs + sl] = t_sh[k][dl][sl];
    }
}

// Encoder: h = relu(x@W1+b1)@W2+b2, then layer-0 tables (buffer 0). grid=512, block=64
__global__ void __launch_bounds__(H) enc_kernel(
    const float* __restrict__ x,
    const float* __restrict__ ew1, const float* __restrict__ eb1,
    const float* __restrict__ ew2, const float* __restrict__ eb2,
    const float* __restrict__ attW1, const float* __restrict__ attB1,
    const float* __restrict__ valW1, const float* __restrict__ valB1)
{
    int d = blockIdx.x, t = threadIdx.x;
    __shared__ float xs[ED], hid[H], hsn[H];
    if (t < ED) xs[t] = x[d * ED + t];
    __syncthreads();
    float a = eb1[t];
#pragma unroll
    for (int k = 0; k < ED; k++) a += xs[k] * ew1[k * H + t];
    hid[t] = fmaxf(a, 0.f);
    __syncthreads();
    float hv = eb2[t];
#pragma unroll 8
    for (int k = 0; k < H; k++) hv += hid[k] * ew2[k * H + t];
    g_h[d * H + t] = hv;
    hsn[t] = hv;
    __syncthreads();
    compute_tables(d, t, 0, hsn, attW1, attB1, valW1, valB1);
}

// Fused layer, 2 dsts per block: block b handles dsts (2b, 2b+1). 256 threads =
// 8 warps; warp w owns srcs [w*64, w*64+64); lane owns the pair (2*lane,+1).
// Pass 1 loads each HsT value ONCE and computes logits for BOTH dsts (halves
// table traffic). Pass 2 loads each Av row once for both dsts. Node phase:
// thread groups [0,128) and [128,256) handle one dst each (weight loads
// dedup through L2). All f32x2 operands pre-duplicated in smem.
__global__ void __launch_bounds__(256, 2) layer_kernel(
    const float* __restrict__ attW1e,   // [6,64] edge rows of att_w1[l]
    const float* __restrict__ attW2,    // [64]
    const float* __restrict__ valW1e,   // [6,64] edge rows of val_w1[l]
    const float* __restrict__ valW2, const float* __restrict__ valB2,
    const float* __restrict__ updW1, const float* __restrict__ updB1,
    const float* __restrict__ updW2, const float* __restrict__ updB2,
    const float* __restrict__ lng, const float* __restrict__ lnb,
    const float* __restrict__ nattW1, const float* __restrict__ nattB1,
    const float* __restrict__ nvalW1, const float* __restrict__ nvalB1,
    const float* __restrict__ decW1, const float* __restrict__ decB1,
    const float* __restrict__ decW2, const float* __restrict__ decB2,
    float* __restrict__ out, int rb, int last)
{
    extern __shared__ __align__(16) char smem_raw[];
    SmemLayout* sm = (SmemLayout*)smem_raw;

    const int dA = 2 * blockIdx.x, dB = dA + 1;
    const int t = threadIdx.x, w = t >> 5, lane = t & 31;
    const int wb = rb ^ 1;

    // Prologue: duplicated weight table + both dsts' Hd rows
    if (t < H) {
        int j = t;
        float w0 = attW1e[0 * H + j], w1 = attW1e[1 * H + j];
        float w2 = attW1e[2 * H + j], w3 = attW1e[3 * H + j];
        float w4 = attW1e[4 * H + j], w5 = attW1e[5 * H + j];
        float wo = attW2[j];
        float hdA = g_Hd[dA * H + j];
        float hdB = g_Hd[dB * H + j];
        sm->wa4[j * 4 + 0] = make_float4(w0, w0, w1, w1);
        sm->wa4[j * 4 + 1] = make_float4(w2, w2, w3, w3);
        sm->wa4[j * 4 + 2] = make_float4(w4, w4, w5, w5);
        sm->wa4[j * 4 + 3] = make_float4(hdA, hdA, hdB, hdB);
        sm->wo2[j] = make_float2(wo, wo);
    }

    const float* HsT = g_HsT[rb];
    const float* AvL = g_Av[rb];
    const int sg = w * 64 + 2 * lane;    // src pair (sg, sg+1)

    // Load ea for both dsts, 2 srcs each (float2 from eaT, contiguous)
    float2 eavA[ED], eavB[ED];
#pragma unroll
    for (int k = 0; k < ED; k++) {
        eavA[k] = *(const float2*)(g_eaT + (size_t)k * EE + dA * NN + sg);
        eavB[k] = *(const float2*)(g_eaT + (size_t)k * EE + dB * NN + sg);
    }

    // Publish duplicated ea pairs for pass 2
    sm->ea2[0][(sg + 0) * 3 + 0] = make_float4(eavA[0].x, eavA[0].x, eavA[1].x, eavA[1].x);
    sm->ea2[0][(sg + 0) * 3 + 1] = make_float4(eavA[2].x, eavA[2].x, eavA[3].x, eavA[3].x);
    sm->ea2[0][(sg + 0) * 3 + 2] = make_float4(eavA[4].x, eavA[4].x, eavA[5].x, eavA[5].x);
    sm->ea2[0][(sg + 1) * 3 + 0] = make_float4(eavA[0].y, eavA[0].y, eavA[1].y, eavA[1].y);
    sm->ea2[0][(sg + 1) * 3 + 1] = make_float4(eavA[2].y, eavA[2].y, eavA[3].y, eavA[3].y);
    sm->ea2[0][(sg + 1) * 3 + 2] = make_float4(eavA[4].y, eavA[4].y, eavA[5].y, eavA[5].y);
    sm->ea2[1][(sg + 0) * 3 + 0] = make_float4(eavB[0].x, eavB[0].x, eavB[1].x, eavB[1].x);
    sm->ea2[1][(sg + 0) * 3 + 1] = make_float4(eavB[2].x, eavB[2].x, eavB[3].x, eavB[3].x);
    sm->ea2[1][(sg + 0) * 3 + 2] = make_float4(eavB[4].x, eavB[4].x, eavB[5].x, eavB[5].x);
    sm->ea2[1][(sg + 1) * 3 + 0] = make_float4(eavB[0].y, eavB[0].y, eavB[1].y, eavB[1].y);
    sm->ea2[1][(sg + 1) * 3 + 1] = make_float4(eavB[2].y, eavB[2].y, eavB[3].y, eavB[3].y);
    sm->ea2[1][(sg + 1) * 3 + 2] = make_float4(eavB[4].y, eavB[4].y, eavB[5].y, eavB[5].y);
    __syncthreads();

    // ---- Pass 1: attention logits for both dsts, full j-loop; hs2 loaded once ----
    float2 lgA = make_float2(0.f, 0.f), lgB = make_float2(0.f, 0.f);
    const float2 c02 = make_float2(0.2f, 0.2f);
#pragma unroll 8
    for (int j = 0; j < H; j++) {
        float4 c0 = sm->wa4[j * 4 + 0];
        float4 c1 = sm->wa4[j * 4 + 1];
        float4 c2 = sm->wa4[j * 4 + 2];
        float4 c3 = sm->wa4[j * 4 + 3];
        float2 wo = sm->wo2[j];
        float2 hs2 = *(const float2*)(HsT + j * NN + sg);
        // dst A: two 3-deep independent chains
        float2 zA  = fadd2(hs2, make_float2(c3.x, c3.y));
        float2 zA2 = fmul2(eavA[3], make_float2(c1.z, c1.w));
        zA  = ffma2(eavA[0], make_float2(c0.x, c0.y), zA);
        zA2 = ffma2(eavA[4], make_float2(c2.x, c2.y), zA2);
        zA  = ffma2(eavA[1], make_float2(c0.z, c0.w), zA);
        zA2 = ffma2(eavA[5], make_float2(c2.z, c2.w), zA2);
        zA  = ffma2(eavA[2], make_float2(c1.x, c1.y), zA);
        zA  = fadd2(zA, zA2);
        // dst B
        float2 zB  = fadd2(hs2, make_float2(c3.z, c3.w));
        float2 zB2 = fmul2(eavB[3], make_float2(c1.z, c1.w));
        zB  = ffma2(eavB[0], make_float2(c0.x, c0.y), zB);
        zB2 = ffma2(eavB[4], make_float2(c2.x, c2.y), zB2);
        zB  = ffma2(eavB[1], make_float2(c0.z, c0.w), zB);
        zB2 = ffma2(eavB[5], make_float2(c2.z, c2.w), zB2);
        zB  = ffma2(eavB[2], make_float2(c1.x, c1.y), zB);
        zB  = fadd2(zB, zB2);
        // leaky_relu(., 0.2) + accumulate
        float2 sA = fmul2(zA, c02);
        float2 sB = fmul2(zB, c02);
        zA.x = fmaxf(zA.x, sA.x); zA.y = fmaxf(zA.y, sA.y);
        zB.x = fmaxf(zB.x, sB.x); zB.y = fmaxf(zB.y, sB.y);
        lgA = ffma2(zA, wo, lgA);
        lgB = ffma2(zB, wo, lgB);
    }

    // ---- Per-warp register softmax (per dst) over this warp's 64 srcs ----
    {
        float mA = warp_max(fmaxf(lgA.x, lgA.y));
        float eA0 = __expf(lgA.x - mA), eA1 = __expf(lgA.y - mA);
        float sA_ = warp_sum(eA0 + eA1);
        float mB = warp_max(fmaxf(lgB.x, lgB.y));
        float eB0 = __expf(lgB.x - mB), eB1 = __expf(lgB.y - mB);
        float sB_ = warp_sum(eB0 + eB1);
        if (lane == 0) {
            sm->pm[0][w] = mA; sm->ps[0][w] = sA_;
            sm->pm[1][w] = mB; sm->ps[1][w] = sB_;
        }
        *(float4*)(&sm->wexp[0][sg]) = make_float4(eA0, eA0, eA1, eA1);
        *(float4*)(&sm->wexp[1][sg]) = make_float4(eB0, eB0, eB1, eB1);
    }
    __syncthreads();

    // ---- Pass 2: alpha-weighted value aggregation for both dsts; Av loaded once ----
    const int j0 = 2 * lane;
    float2 wv[ED];
#pragma unroll
    for (int k = 0; k < ED; k++) wv[k] = *(const float2*)(valW1e + k * H + j0);

    float2 accA = make_float2(0.f, 0.f), accB = make_float2(0.f, 0.f);
    const int base = w * 64;
    const float* avbase = AvL + j0;
#pragma unroll 4
    for (int i = 0; i < 64; i++) {
        int s = base + i;
        float2 p0 = *(const float2*)(avbase + (size_t)s * H);
        // dst A
        float4 qA0 = sm->ea2[0][s * 3 + 0];
        float4 qA1 = sm->ea2[0][s * 3 + 1];
        float4 qA2 = sm->ea2[0][s * 3 + 2];
        float2 pA = p0;
        pA = ffma2(make_float2(qA0.x, qA0.y), wv[0], pA);
        pA = ffma2(make_float2(qA0.z, qA0.w), wv[1], pA);
        pA = ffma2(make_float2(qA1.x, qA1.y), wv[2], pA);
        pA = ffma2(make_float2(qA1.z, qA1.w), wv[3], pA);
        pA = ffma2(make_float2(qA2.x, qA2.y), wv[4], pA);
        pA = ffma2(make_float2(qA2.z, qA2.w), wv[5], pA);
        pA.x = fmaxf(pA.x, 0.f); pA.y = fmaxf(pA.y, 0.f);
        accA = ffma2(sm->wexp[0][s], pA, accA);
        // dst B
        float4 qB0 = sm->ea2[1][s * 3 + 0];
        float4 qB1 = sm->ea2[1][s * 3 + 1];
        float4 qB2 = sm->ea2[1][s * 3 + 2];
        float2 pB = p0;
        pB = ffma2(make_float2(qB0.x, qB0.y), wv[0], pB);
        pB = ffma2(make_float2(qB0.z, qB0.w), wv[1], pB);
        pB = ffma2(make_float2(qB1.x, qB1.y), wv[2], pB);
        pB = ffma2(make_float2(qB1.z, qB1.w), wv[3], pB);
        pB = ffma2(make_float2(qB2.x, qB2.y), wv[4], pB);
        pB = ffma2(make_float2(qB2.z, qB2.w), wv[5], pB);
        pB.x = fmaxf(pB.x, 0.f); pB.y = fmaxf(pB.y, 0.f);
        accB = ffma2(sm->wexp[1][s], pB, accB);
    }
    *(float2*)(&sm->pacc[0][w * H + j0]) = accA;
    *(float2*)(&sm->pacc[1][w * H + j0]) = accB;
    __syncthreads();

    // ---- Node phase: group g = t>>7 handles dst (dA + g) with 128 threads ----
    const int g = t >> 7, tl = t & 127;
    const int dg = dA + g;
    const int o = tl & 63, q = tl >> 6;

    // Combine 8 warp softmax partials (64 threads per group)
    if (tl < H) {
        float M = sm->pm[g][0];
#pragma unroll
        for (int k = 1; k < 8; k++) M = fmaxf(M, sm->pm[g][k]);
        float stot = 0.f, a = 0.f;
#pragma unroll
        for (int k = 0; k < 8; k++) {
            float sc = __expf(sm->pm[g][k] - M);
            stot += sm->ps[g][k] * sc;
            a    += sm->pacc[g][k * H + tl] * sc;
        }
        sm->agg[g][tl] = a / stot;
        sm->hsm[g][tl] = g_h[dg * H + tl];
    }
    __syncthreads();

    // stage 1: tmp = val_b2 + agg @ val_w2 (2-way k-split per group)
    {
        float p = 0.f;
        int k0 = q * 32;
#pragma unroll
        for (int kk = 0; kk < 32; kk++) p += sm->agg[g][k0 + kk] * valW2[(k0 + kk) * H + o];
        sm->part[g][q * H + o] = p;
    }
    __syncthreads();
    if (tl < H) sm->tmp[g][tl] = valB2[tl] + sm->part[g][tl] + sm->part[g][H + tl];
    __syncthreads();

    // stage 2: hid = relu(upd_b1 + [h,tmp] @ upd_w1)
    {
        const float* srcv = (q == 0) ? sm->hsm[g] : sm->tmp[g];
        int rbase = q * H;
        float p = 0.f;
#pragma unroll
        for (int kk = 0; kk < 64; kk++) p += srcv[kk] * updW1[(rbase + kk) * H + o];
        sm->part[g][q * H + o] = p;
    }
    __syncthreads();
    if (tl < H) sm->hid[g][tl] = fmaxf(updB1[tl] + sm->part[g][tl] + sm->part[g][H + tl], 0.f);
    __syncthreads();

    // stage 3: u = upd_b2 + hid @ upd_w2
    {
        float p = 0.f;
        int k0 = q * 32;
#pragma unroll
        for (int kk = 0; kk < 32; kk++) p += sm->hid[g][k0 + kk] * updW2[(k0 + kk) * H + o];
        sm->part[g][q * H + o] = p;
    }
    __syncthreads();

    // residual + LayerNorm (threads tl<64 of each group; fused sum/sumsq)
    float r = 0.f, dr = 0.f;
    const int wg2 = tl >> 5;   // warp-in-group for tl<64: 0 or 1
    if (tl < H) {
        float u = updB2[tl] + sm->part[g][tl] + sm->part[g][H + tl];
        r = u + sm->hsm[g][tl];
        float s1 = warp_sum(r);
        float s2 = warp_sum(r * r);
        if (lane == 0) { sm->red[g][wg2] = s1; sm->red[g][wg2 + 2] = s2; }
    }
    __syncthreads();
    if (tl < H) {
        float mu  = (sm->red[g][0] + sm->red[g][1]) * (1.0f / H);
        float ex2 = (sm->red[g][2] + sm->red[g][3]) * (1.0f / H);
        float var = ex2 - mu * mu;
        dr = r - mu;
        float hn = lng[tl] * dr * rsqrtf(var + LN_EPS) + lnb[tl];
        sm->hn[g][tl] = hn;
        if (!last) g_h[dg * H + tl] = hn;
    }
    __syncthreads();

    if (!last) {
        if (tl < H)
            compute_tables(dg, tl, wb, sm->hn[g], nattW1, nattB1, nvalW1, nvalB1);
    } else {
        if (tl < H) {
            float dh = decB1[tl];
#pragma unroll 8
            for (int k = 0; k < H; k++) dh += sm->hn[g][k] * decW1[k * H + tl];
            dh = fmaxf(dh, 0.f);
            float p = dh * decW2[tl];
            float psum = warp_sum(p);
            if (lane == 0) sm->red[g][wg2] = psum;
        }
        __syncthreads();
        if (tl == 0) out[dg] = sm->red[g][0] + sm->red[g][1] + decB2[0];
    }
}

extern "C" void kernel_launch(void* const* d_in, const int* in_sizes, int n_in,
                              void* d_out, int out_size)
{
    const float* x      = (const float*)d_in[0];
    const float* ea     = (const float*)d_in[1];
    const float* enc_w1 = (const float*)d_in[2];
    const float* enc_b1 = (const float*)d_in[3];
    const float* enc_w2 = (const float*)d_in[4];
    const float* enc_b2 = (const float*)d_in[5];
    const float* att_w1 = (const float*)d_in[6];   // [4,134,64]
    const float* att_b1 = (const float*)d_in[7];   // [4,64]
    const float* att_w2 = (const float*)d_in[8];   // [4,64,1]
    // d_in[9] = att_b2 — cancels inside softmax, unused
    const float* val_w1 = (const float*)d_in[10];  // [4,70,64]
    const float* val_b1 = (const float*)d_in[11];  // [4,64]
    const float* val_w2 = (const float*)d_in[12];  // [4,64,64]
    const float* val_b2 = (const float*)d_in[13];  // [4,64]
    const float* upd_w1 = (const float*)d_in[14];  // [4,128,64]
    const float* upd_b1 = (const float*)d_in[15];  // [4,64]
    const float* upd_w2 = (const float*)d_in[16];  // [4,64,64]
    const float* upd_b2 = (const float*)d_in[17];  // [4,64]
    const float* ln_g   = (const float*)d_in[18];  // [4,64]
    const float* ln_b   = (const float*)d_in[19];  // [4,64]
    const float* dec_w1 = (const float*)d_in[20];
    const float* dec_b1 = (const float*)d_in[21];
    const float* dec_w2 = (const float*)d_in[22];
    const float* dec_b2 = (const float*)d_in[23];
    // d_in[24] = edge_index: src=e/512, dst=e%512 (structure exploited directly)

    float* out = (float*)d_out;

    static_assert(sizeof(SmemLayout) < 100 * 1024, "smem too big");
    cudaFuncSetAttribute(layer_kernel, cudaFuncAttributeMaxDynamicSharedMemorySize,
                         (int)sizeof(SmemLayout));

    ea_transpose_kernel<<<dim3(16, 16), 256>>>(ea);
    enc_kernel<<<NN, H>>>(x, enc_w1, enc_b1, enc_w2, enc_b2,
                          att_w1, att_b1, val_w1, val_b1);

    for (int l = 0; l < NL; l++) {
        int last = (l == NL - 1);
        int nl = (l + 1) % NL;      // dummy-but-valid pointers on last layer
        int rb = l & 1;             // enc wrote buffer 0; layer l reads l&1, writes (l&1)^1
        layer_kernel<<<NN / 2, 256, sizeof(SmemLayout)>>>(
                                  att_w1 + (l * 134 + 128) * H,
                                  att_w2 + l * H,
                                  val_w1 + (l * 70 + 64) * H,
                                  val_w2 + l * H * H, val_b2 + l * H,
                                  upd_w1 + l * 2 * H * H, upd_b1 + l * H,
                                  upd_w2 + l * H * H, upd_b2 + l * H,
                                  ln_g + l * H, ln_b + l * H,
                                  att_w1 + nl * 134 * H, att_b1 + nl * H,
                                  val_w1 + nl * 70 * H, val_b1 + nl * H,
                                  dec_w1, dec_b1, dec_w2, dec_b2,
                                  out, rb, last);
    }
}